// round 13
// baseline (speedup 1.0000x reference)
#include <cuda_runtime.h>
#include <cuda_bf16.h>
#include <mma.h>
#include <cstdint>

using namespace nvcuda;

#define BB 64
#define TT 4096
#define DD 128
#define HH 128
#define GG 384            // 3*H, gates [r, z, n]
#define APAD 136          // padded act row (elems) for conflict-free LDSM

typedef unsigned long long u64;
typedef unsigned int u32;

// ---------------- scratch (device globals; no allocation) -------------------
__device__ float g_gi0[(size_t)TT * BB * GG];   // raw gi (NO b_ih; rec adds it)
__device__ float g_gi1[(size_t)TT * BB * GG];
__device__ float g_h0 [(size_t)TT * BB * HH];
// bf16 hi/lo W images, row-major [384][128] per layer
__device__ __nv_bfloat16 g_wh[2][384 * 128];
__device__ __nv_bfloat16 g_wl[2][384 * 128];

// ---------------- helpers ---------------------------------------------------
__device__ __forceinline__ u64 fma2p(u64 d, u64 a, u64 b) {
    asm("fma.rn.f32x2 %0, %1, %2, %0;" : "+l"(d) : "l"(a), "l"(b)); return d;
}
__device__ __forceinline__ float fsig(float x) {
    return __fdividef(1.0f, 1.0f + __expf(-x));
}
__device__ __forceinline__ float ftanh(float x) {
    return 1.0f - __fdividef(2.0f, __expf(2.0f * x) + 1.0f);
}
__device__ __forceinline__ void split_pack(float x0, float x1, u32& hi, u32& lo) {
    __nv_bfloat16 h0 = __float2bfloat16(x0);
    __nv_bfloat16 h1 = __float2bfloat16(x1);
    __nv_bfloat16 l0 = __float2bfloat16(x0 - __bfloat162float(h0));
    __nv_bfloat16 l1 = __float2bfloat16(x1 - __bfloat162float(h1));
    hi = (u32)__bfloat16_as_ushort(h0) | ((u32)__bfloat16_as_ushort(h1) << 16);
    lo = (u32)__bfloat16_as_ushort(l0) | ((u32)__bfloat16_as_ushort(l1) << 16);
}

// ---------------- conversion: W -> bf16 hi/lo images ------------------------
__global__ void conv_w(const float* __restrict__ W0, const float* __restrict__ W1) {
    int i = blockIdx.x * blockDim.x + threadIdx.x;
    if (i >= 2 * 384 * 64) return;
    const int L = i / (384 * 64);
    const int rem = i % (384 * 64);
    const int j = rem >> 6;
    const int p = rem & 63;
    const float* W = L ? W1 : W0;
    u32 hi, lo;
    split_pack(W[(size_t)j * 128 + 2 * p], W[(size_t)j * 128 + 2 * p + 1], hi, lo);
    *(u32*)&g_wh[L][j * 128 + 2 * p] = hi;
    *(u32*)&g_wl[L][j * 128 + 2 * p] = lo;
}

// ---------------- WMMA GEMM (R12 winner) -------------------------------------
// D[t][b][mtile*128+j] = sum_k W[j,k]*act[b,k], 3-term bf16 split, fp32 acc.
// W hi/lo fragments preloaded in registers; act staged to padded smem with
// inline fp32->bf16 hi/lo split.
__global__ void __launch_bounds__(256, 1) gemm_wmma(
    const float* __restrict__ act,
    int actMode,                     // 0: x layout [b][TT][128]; 1: h0 layout [t][b][128]
    const __nv_bfloat16* __restrict__ wh, const __nv_bfloat16* __restrict__ wl,
    float* __restrict__ dst, int t0, int t1, int nstripes)
{
    __shared__ __align__(16) __nv_bfloat16 s_ah[64 * APAD];
    __shared__ __align__(16) __nv_bfloat16 s_al[64 * APAD];
    const int tid = threadIdx.x;
    const int warp = tid >> 5;
    const int mtile = blockIdx.x / nstripes;
    const int stripe = blockIdx.x % nstripes;
    const int j0 = mtile * 128 + warp * 16;

    wmma::fragment<wmma::matrix_a, 16, 16, 16, __nv_bfloat16, wmma::row_major> wf_h[8], wf_l[8];
    #pragma unroll
    for (int k = 0; k < 8; k++) {
        wmma::load_matrix_sync(wf_h[k], wh + (size_t)j0 * 128 + k * 16, 128);
        wmma::load_matrix_sync(wf_l[k], wl + (size_t)j0 * 128 + k * 16, 128);
    }

    for (int t = t0 + stripe; t < t1; t += nstripes) {
        for (int i = tid; i < 64 * 32; i += 256) {       // units of 4 floats
            const int b = i >> 5;
            const int kq = (i & 31) * 4;
            const float* src = (actMode == 0)
                ? act + ((size_t)b * TT + t) * DD + kq
                : act + ((size_t)t * BB + b) * HH + kq;
            float4 v = *(const float4*)src;
            u32 h0, l0, h1, l1;
            split_pack(v.x, v.y, h0, l0);
            split_pack(v.z, v.w, h1, l1);
            *(u32*)&s_ah[b * APAD + kq]     = h0;
            *(u32*)&s_ah[b * APAD + kq + 2] = h1;
            *(u32*)&s_al[b * APAD + kq]     = l0;
            *(u32*)&s_al[b * APAD + kq + 2] = l1;
        }
        __syncthreads();

        wmma::fragment<wmma::accumulator, 16, 16, 16, float> acc[4];
        #pragma unroll
        for (int n = 0; n < 4; n++) wmma::fill_fragment(acc[n], 0.0f);

        #pragma unroll
        for (int k = 0; k < 8; k++) {
            #pragma unroll
            for (int n = 0; n < 4; n++) {
                wmma::fragment<wmma::matrix_b, 16, 16, 16, __nv_bfloat16, wmma::col_major> bh, bl;
                wmma::load_matrix_sync(bh, s_ah + n * 16 * APAD + k * 16, APAD);
                wmma::load_matrix_sync(bl, s_al + n * 16 * APAD + k * 16, APAD);
                wmma::mma_sync(acc[n], wf_h[k], bh, acc[n]);   // xh*wh
                wmma::mma_sync(acc[n], wf_h[k], bl, acc[n]);   // xl*wh
                wmma::mma_sync(acc[n], wf_l[k], bh, acc[n]);   // xh*wl
            }
        }

        float* dp = dst + (size_t)t * BB * GG + j0;
        #pragma unroll
        for (int n = 0; n < 4; n++)
            wmma::store_matrix_sync(dp + (size_t)(n * 16) * GG, acc[n],
                                    GG, wmma::mem_col_major);
        __syncthreads();
    }
}

// ---------------- monolithic rec (4096 steps, 1 batch/CTA) -------------------
// Roles: j<128 r-rows (+final gate math), 128-255 z-rows (z pre-computed
// pre-barrier), 256-383 n-rows (raw gh_n). Post-barrier chain: tanh + blend.
__global__ __launch_bounds__(384, 1) void rec_mono(
    const float* __restrict__ Whh,
    const float* __restrict__ bhh,
    const float* __restrict__ bih,
    int layer,
    float* __restrict__ hout)
{
    const int j = threadIdx.x;
    const int e = j & 127;
    const int role = j >> 7;               // 0=r, 1=z, 2=n
    const int b = blockIdx.x;

    u64 w[64];
    {
        const ulonglong2* wr = (const ulonglong2*)(Whh + (size_t)j * 128);
        #pragma unroll
        for (int k = 0; k < 32; k++) { ulonglong2 v = wr[k]; w[2*k] = v.x; w[2*k+1] = v.y; }
    }
    const float bj = bhh[j];

    const float* gi = layer ? g_gi1 : g_gi0;
    const size_t S = (size_t)BB * GG;
    const float* pOwn = gi + (size_t)b * GG + j;          // r,z rows
    const float* pN   = gi + (size_t)b * GG + 256 + e;    // r-rows also stream gi_n
    const float biOwn = (role < 2) ? bih[j] : 0.0f;
    const float biN   = (role == 0) ? bih[256 + e] : 0.0f;

    __shared__ __align__(16) float s_h[128];
    __shared__ float s_z[128];
    __shared__ float s_ghn[128];

    if (j < 128) s_h[j] = 0.0f;
    __syncthreads();

    // distance-2 gi prefetch state
    float gOwn0 = 0.f, gOwn1 = 0.f, gN0 = 0.f, gN1 = 0.f;
    if (role < 2)  { gOwn0 = pOwn[0]; gOwn1 = pOwn[S]; }
    if (role == 0) { gN0 = pN[0]; gN1 = pN[S]; }

    float hreg = 0.0f;
    const ulonglong2* h16 = (const ulonglong2*)s_h;
    float* h0p = g_h0 + (size_t)b * HH + e;

    for (int t = 0; t < TT; t++) {
        // dot: gh row j = b_hh[j] + h . W_hh[j]  (4 fma2 chains)
        u64 a0, a1 = 0, a2 = 0, a3 = 0;
        asm("mov.b64 %0, {%1,%2};" : "=l"(a0) : "f"(bj), "f"(0.0f));
        #pragma unroll
        for (int k = 0; k < 16; k++) {
            ulonglong2 v0 = h16[2*k], v1 = h16[2*k+1];
            a0 = fma2p(a0, v0.x, w[4*k]);
            a1 = fma2p(a1, v0.y, w[4*k+1]);
            a2 = fma2p(a2, v1.x, w[4*k+2]);
            a3 = fma2p(a3, v1.y, w[4*k+3]);
        }
        float acc;
        {
            float p0, p1, p2, p3, p4, p5, p6, p7;
            asm("mov.b64 {%0,%1}, %2;" : "=f"(p0), "=f"(p1) : "l"(a0));
            asm("mov.b64 {%0,%1}, %2;" : "=f"(p2), "=f"(p3) : "l"(a1));
            asm("mov.b64 {%0,%1}, %2;" : "=f"(p4), "=f"(p5) : "l"(a2));
            asm("mov.b64 {%0,%1}, %2;" : "=f"(p6), "=f"(p7) : "l"(a3));
            acc = ((p0 + p1) + (p2 + p3)) + ((p4 + p5) + (p6 + p7));
        }

        float r = 0.0f;
        if (role == 0) {
            r = fsig(acc + gOwn0 + biOwn);          // register-only, pre-barrier
        } else if (role == 1) {
            s_z[e] = fsig(acc + gOwn0 + biOwn);     // z fully pre-computed
        } else {
            s_ghn[e] = acc;                          // raw gh_n
        }
        __syncthreads();                             // (A)

        if (role == 0) {
            const float n = ftanh(gN0 + biN + r * s_ghn[e]);
            hreg = n + s_z[e] * (hreg - n);
            s_h[e] = hreg;
            if (layer == 0) h0p[(size_t)t * BB * HH] = hreg;
        }
        __syncthreads();                             // (B)

        // shift prefetch window, load t+2
        if (t + 2 < TT) {
            const size_t off = (size_t)(t + 2) * S;
            if (role < 2)  { gOwn0 = gOwn1; gOwn1 = pOwn[off]; }
            if (role == 0) { gN0 = gN1; gN1 = pN[off]; }
        } else {
            gOwn0 = gOwn1; gN0 = gN1;
        }
    }

    if (role == 0) hout[(size_t)b * HH + e] = hreg;
}

// ---------------- launch (fully serial, default stream) ----------------------
extern "C" void kernel_launch(void* const* d_in, const int* in_sizes, int n_in,
                              void* d_out, int out_size)
{
    const float* x     = (const float*)d_in[0];
    const float* W_ih0 = (const float*)d_in[1];
    const float* W_hh0 = (const float*)d_in[2];
    const float* b_ih0 = (const float*)d_in[3];
    const float* b_hh0 = (const float*)d_in[4];
    const float* W_ih1 = (const float*)d_in[5];
    const float* W_hh1 = (const float*)d_in[6];
    const float* b_ih1 = (const float*)d_in[7];
    const float* b_hh1 = (const float*)d_in[8];
    float* out = (float*)d_out;   // [L=2, B, H]

    static bool inited = false;
    static __nv_bfloat16 *p_wh0, *p_wl0, *p_wh1, *p_wl1;
    static float *p_gi0, *p_gi1, *p_h0;
    if (!inited) {
        void* p;
        cudaGetSymbolAddress(&p, g_wh);  p_wh0 = (__nv_bfloat16*)p; p_wh1 = p_wh0 + 384 * 128;
        cudaGetSymbolAddress(&p, g_wl);  p_wl0 = (__nv_bfloat16*)p; p_wl1 = p_wl0 + 384 * 128;
        cudaGetSymbolAddress(&p, g_gi0); p_gi0 = (float*)p;
        cudaGetSymbolAddress(&p, g_gi1); p_gi1 = (float*)p;
        cudaGetSymbolAddress(&p, g_h0);  p_h0  = (float*)p;
        inited = true;
    }

    conv_w<<<(2 * 384 * 64 + 255) / 256, 256>>>(W_ih0, W_ih1);
    gemm_wmma<<<3 * 48, 256>>>(x, /*actMode=*/0, p_wh0, p_wl0, p_gi0, 0, TT, 48);
    rec_mono<<<64, 384>>>(W_hh0, b_hh0, b_ih0, /*layer=*/0, out);
    gemm_wmma<<<3 * 48, 256>>>(p_h0, /*actMode=*/1, p_wh1, p_wl1, p_gi1, 0, TT, 48);
    rec_mono<<<64, 384>>>(W_hh1, b_hh1, b_ih1, /*layer=*/1, out + BB * HH);
}

// round 14
// speedup vs baseline: 1.7007x; 1.7007x over previous
#include <cuda_runtime.h>
#include <cuda_bf16.h>
#include <mma.h>
#include <cstdint>

using namespace nvcuda;

#define BB 64
#define TT 4096
#define DD 128
#define HH 128
#define GG 384            // 3*H, gates [r, z, n]

#define NC 16             // chunks
#define CC 256            // timesteps per chunk
#define APAD 136          // padded act row (elems) for conflict-free LDSM

typedef unsigned long long u64;
typedef unsigned int u32;

// ---------------- scratch (device globals; no allocation) -------------------
__device__ float g_gi0[(size_t)TT * BB * GG];   // raw gi (NO b_ih; rec adds it)
__device__ float g_gi1[(size_t)TT * BB * GG];
__device__ float g_h0 [(size_t)TT * BB * HH];
__device__ float g_hst1[BB * HH];
// bf16 hi/lo W images, row-major [384][128] per layer
__device__ __nv_bfloat16 g_wh[2][384 * 128];
__device__ __nv_bfloat16 g_wl[2][384 * 128];

// ---------------- helpers ---------------------------------------------------
__device__ __forceinline__ u64 fma2p(u64 d, u64 a, u64 b) {
    asm("fma.rn.f32x2 %0, %1, %2, %0;" : "+l"(d) : "l"(a), "l"(b)); return d;
}
__device__ __forceinline__ float fsig(float x) {
    return __fdividef(1.0f, 1.0f + __expf(-x));
}
__device__ __forceinline__ float ftanh(float x) {
    return 1.0f - __fdividef(2.0f, __expf(2.0f * x) + 1.0f);
}
__device__ __forceinline__ void split_pack(float x0, float x1, u32& hi, u32& lo) {
    __nv_bfloat16 h0 = __float2bfloat16(x0);
    __nv_bfloat16 h1 = __float2bfloat16(x1);
    __nv_bfloat16 l0 = __float2bfloat16(x0 - __bfloat162float(h0));
    __nv_bfloat16 l1 = __float2bfloat16(x1 - __bfloat162float(h1));
    hi = (u32)__bfloat16_as_ushort(h0) | ((u32)__bfloat16_as_ushort(h1) << 16);
    lo = (u32)__bfloat16_as_ushort(l0) | ((u32)__bfloat16_as_ushort(l1) << 16);
}

// ---------------- conversion: W -> bf16 hi/lo images ------------------------
__global__ void conv_w(const float* __restrict__ W0, const float* __restrict__ W1) {
    int i = blockIdx.x * blockDim.x + threadIdx.x;
    if (i >= 2 * 384 * 64) return;
    const int L = i / (384 * 64);
    const int rem = i % (384 * 64);
    const int j = rem >> 6;
    const int p = rem & 63;
    const float* W = L ? W1 : W0;
    u32 hi, lo;
    split_pack(W[(size_t)j * 128 + 2 * p], W[(size_t)j * 128 + 2 * p + 1], hi, lo);
    *(u32*)&g_wh[L][j * 128 + 2 * p] = hi;
    *(u32*)&g_wl[L][j * 128 + 2 * p] = lo;
}

// ---------------- WMMA GEMM (R12 winner, unchanged) --------------------------
__global__ void __launch_bounds__(256, 1) gemm_wmma(
    const float* __restrict__ act,
    int actMode,                     // 0: x layout [b][TT][128]; 1: h0 layout [t][b][128]
    const __nv_bfloat16* __restrict__ wh, const __nv_bfloat16* __restrict__ wl,
    float* __restrict__ dst, int t0, int t1, int nstripes)
{
    __shared__ __align__(16) __nv_bfloat16 s_ah[64 * APAD];
    __shared__ __align__(16) __nv_bfloat16 s_al[64 * APAD];
    const int tid = threadIdx.x;
    const int warp = tid >> 5;
    const int mtile = blockIdx.x / nstripes;
    const int stripe = blockIdx.x % nstripes;
    const int j0 = mtile * 128 + warp * 16;

    wmma::fragment<wmma::matrix_a, 16, 16, 16, __nv_bfloat16, wmma::row_major> wf_h[8], wf_l[8];
    #pragma unroll
    for (int k = 0; k < 8; k++) {
        wmma::load_matrix_sync(wf_h[k], wh + (size_t)j0 * 128 + k * 16, 128);
        wmma::load_matrix_sync(wf_l[k], wl + (size_t)j0 * 128 + k * 16, 128);
    }

    for (int t = t0 + stripe; t < t1; t += nstripes) {
        for (int i = tid; i < 64 * 32; i += 256) {       // units of 4 floats
            const int b = i >> 5;
            const int kq = (i & 31) * 4;
            const float* src = (actMode == 0)
                ? act + ((size_t)b * TT + t) * DD + kq
                : act + ((size_t)t * BB + b) * HH + kq;
            float4 v = *(const float4*)src;
            u32 h0, l0, h1, l1;
            split_pack(v.x, v.y, h0, l0);
            split_pack(v.z, v.w, h1, l1);
            *(u32*)&s_ah[b * APAD + kq]     = h0;
            *(u32*)&s_ah[b * APAD + kq + 2] = h1;
            *(u32*)&s_al[b * APAD + kq]     = l0;
            *(u32*)&s_al[b * APAD + kq + 2] = l1;
        }
        __syncthreads();

        wmma::fragment<wmma::accumulator, 16, 16, 16, float> acc[4];
        #pragma unroll
        for (int n = 0; n < 4; n++) wmma::fill_fragment(acc[n], 0.0f);

        #pragma unroll
        for (int k = 0; k < 8; k++) {
            #pragma unroll
            for (int n = 0; n < 4; n++) {
                wmma::fragment<wmma::matrix_b, 16, 16, 16, __nv_bfloat16, wmma::col_major> bh, bl;
                wmma::load_matrix_sync(bh, s_ah + n * 16 * APAD + k * 16, APAD);
                wmma::load_matrix_sync(bl, s_al + n * 16 * APAD + k * 16, APAD);
                wmma::mma_sync(acc[n], wf_h[k], bh, acc[n]);   // xh*wh
                wmma::mma_sync(acc[n], wf_h[k], bl, acc[n]);   // xl*wh
                wmma::mma_sync(acc[n], wf_l[k], bh, acc[n]);   // xh*wl
            }
        }

        float* dp = dst + (size_t)t * BB * GG + j0;
        #pragma unroll
        for (int n = 0; n < 4; n++)
            wmma::store_matrix_sync(dp + (size_t)(n * 16) * GG, acc[n],
                                    GG, wmma::mem_col_major);
        __syncthreads();
    }
}

// ---------------- rec chunk — R2-faithful inner loop -------------------------
// One gi stream per thread (thread j covers gi index j; 1 bare load/step).
// Bias added at USE site (after the dot), never fused with the load.
// All threads store s_gh; n-rows relay their gi via s_gin. All gate math
// post-barrier on threads 0-127 (exact R2 structure).
__global__ __launch_bounds__(384, 1) void rec_chunk(
    const float* __restrict__ Whh,
    const float* __restrict__ bhh,
    const float* __restrict__ bih,
    int layer, int c,
    float* __restrict__ hout)
{
    const int j = threadIdx.x;
    const int e = j & 127;
    const bool isGate = (j < 128);
    const int b = blockIdx.x;

    u64 w[64];
    {
        const ulonglong2* wr = (const ulonglong2*)(Whh + (size_t)j * 128);
        #pragma unroll
        for (int k = 0; k < 32; k++) { ulonglong2 v = wr[k]; w[2*k] = v.x; w[2*k+1] = v.y; }
    }
    const float bj = bhh[j];
    const float biOwn = bih[j];

    const float* gi = layer ? g_gi1 : g_gi0;
    const size_t S = (size_t)BB * GG;
    const float* pOwn = gi + (size_t)b * GG + j;

    __shared__ __align__(16) float s_h[128];
    __shared__ float s_gh[384];
    __shared__ float s_gin[128];

    const int t0 = c * CC, t1 = t0 + CC;

    float hreg = 0.0f;
    if (isGate) {
        if (c == 0) hreg = 0.0f;
        else if (layer == 0) hreg = g_h0[((size_t)(t0 - 1) * BB + b) * HH + e];
        else hreg = g_hst1[b * HH + e];
        s_h[e] = hreg;
    }
    __syncthreads();

    float gval = pOwn[(size_t)t0 * S];       // bare load
    float* h0p = g_h0 + (size_t)b * HH + e;
    const ulonglong2* h16 = (const ulonglong2*)s_h;

    for (int t = t0; t < t1; t++) {
        // dot: gh row j = b_hh[j] + h . W_hh[j]   (2 fma2 chains, R2-exact)
        u64 a0, a1 = 0;
        asm("mov.b64 %0, {%1,%2};" : "=l"(a0) : "f"(bj), "f"(0.0f));
        #pragma unroll
        for (int k = 0; k < 32; k++) {
            ulonglong2 v = h16[k];
            a0 = fma2p(a0, v.x, w[2*k]);
            a1 = fma2p(a1, v.y, w[2*k+1]);
        }
        float acc;
        {
            float xl, xh, yl, yh;
            asm("mov.b64 {%0,%1}, %2;" : "=f"(xl), "=f"(xh) : "l"(a0));
            asm("mov.b64 {%0,%1}, %2;" : "=f"(yl), "=f"(yh) : "l"(a1));
            acc = (xl + xh) + (yl + yh);
        }

        const float gpb = gval + biOwn;      // bias at use, after the dot
        if (j < 256) {
            s_gh[j] = acc + gpb;             // r,z rows: gi + gh fused
        } else {
            s_gh[j] = acc;                   // n rows: keep gh separate
            s_gin[j - 256] = gpb;
        }
        __syncthreads();                     // (A) gh ready

        if (isGate) {
            const float r = fsig(s_gh[e]);
            const float z = fsig(s_gh[e + 128]);
            const float n = ftanh(s_gin[e] + r * s_gh[e + 256]);
            hreg = n + z * (hreg - n);
            s_h[e] = hreg;
            if (layer == 0) h0p[(size_t)t * BB * HH] = hreg;
        }
        __syncthreads();                     // (B) h published

        if (t + 1 < t1)
            gval = pOwn[(size_t)(t + 1) * S];    // bare load, no arithmetic
    }

    if (isGate) {
        if (layer == 1) g_hst1[b * HH + e] = hreg;
        if (c == NC - 1) hout[(size_t)b * HH + e] = hreg;
    }
}

// ---------------- launch (R12 topology, unchanged) ---------------------------
extern "C" void kernel_launch(void* const* d_in, const int* in_sizes, int n_in,
                              void* d_out, int out_size)
{
    const float* x     = (const float*)d_in[0];
    const float* W_ih0 = (const float*)d_in[1];
    const float* W_hh0 = (const float*)d_in[2];
    const float* b_ih0 = (const float*)d_in[3];
    const float* b_hh0 = (const float*)d_in[4];
    const float* W_ih1 = (const float*)d_in[5];
    const float* W_hh1 = (const float*)d_in[6];
    const float* b_ih1 = (const float*)d_in[7];
    const float* b_hh1 = (const float*)d_in[8];
    float* out = (float*)d_out;   // [L=2, B, H]

    static bool inited = false;
    static cudaStream_t sB, sC;
    static cudaEvent_t evFork, evG0, evR0[NC], evG1[NC];
    static __nv_bfloat16 *p_wh0, *p_wl0, *p_wh1, *p_wl1;
    static float *p_gi0, *p_gi1, *p_h0;
    if (!inited) {
        cudaStreamCreateWithFlags(&sB, cudaStreamNonBlocking);
        cudaStreamCreateWithFlags(&sC, cudaStreamNonBlocking);
        cudaEventCreateWithFlags(&evFork, cudaEventDisableTiming);
        cudaEventCreateWithFlags(&evG0, cudaEventDisableTiming);
        for (int i = 0; i < NC; i++) {
            cudaEventCreateWithFlags(&evR0[i], cudaEventDisableTiming);
            cudaEventCreateWithFlags(&evG1[i], cudaEventDisableTiming);
        }
        void* p;
        cudaGetSymbolAddress(&p, g_wh);  p_wh0 = (__nv_bfloat16*)p; p_wh1 = p_wh0 + 384 * 128;
        cudaGetSymbolAddress(&p, g_wl);  p_wl0 = (__nv_bfloat16*)p; p_wl1 = p_wl0 + 384 * 128;
        cudaGetSymbolAddress(&p, g_gi0); p_gi0 = (float*)p;
        cudaGetSymbolAddress(&p, g_gi1); p_gi1 = (float*)p;
        cudaGetSymbolAddress(&p, g_h0);  p_h0  = (float*)p;
        inited = true;
    }

    cudaEventRecord(evFork, 0);
    cudaStreamWaitEvent(sB, evFork, 0);
    cudaStreamWaitEvent(sC, evFork, 0);

    // Up-front: W conversion + ALL of gi0 (144 CTAs, then gone).
    conv_w<<<(2 * 384 * 64 + 255) / 256, 256, 0, sB>>>(W_ih0, W_ih1);
    gemm_wmma<<<3 * 48, 256, 0, sB>>>(x, /*actMode=*/0, p_wh0, p_wl0,
                                      p_gi0, 0, TT, 48);
    cudaEventRecord(evG0, sB);
    cudaStreamWaitEvent(sC, evG0, 0);

    for (int c = 0; c < NC; c++) {
        rec_chunk<<<64, 384, 0, sB>>>(W_hh0, b_hh0, b_ih0, /*layer=*/0, c, out);
        cudaEventRecord(evR0[c], sB);
    }
    for (int c = 0; c < NC; c++) {
        cudaStreamWaitEvent(sC, evR0[c], 0);
        gemm_wmma<<<3 * 4, 256, 0, sC>>>(p_h0, /*actMode=*/1, p_wh1, p_wl1,
                                         p_gi1, c * CC, (c + 1) * CC, 4);
        cudaEventRecord(evG1[c], sC);
    }
    for (int c = 0; c < NC; c++) {
        cudaStreamWaitEvent(0, evG1[c], 0);
        rec_chunk<<<64, 384, 0, 0>>>(W_hh1, b_hh1, b_ih1, /*layer=*/1, c, out + BB * HH);
    }
}

// round 15
// speedup vs baseline: 1.7290x; 1.0166x over previous
#include <cuda_runtime.h>
#include <cuda_bf16.h>
#include <mma.h>
#include <cstdint>

using namespace nvcuda;

#define BB 64
#define TT 4096
#define DD 128
#define HH 128
#define GG 384            // 3*H, gates [r, z, n]

#define NC 16             // chunks
#define CC 256            // timesteps per chunk
#define APAD 136          // padded act row (elems) for conflict-free LDSM

typedef unsigned long long u64;
typedef unsigned int u32;

// ---------------- scratch (device globals; no allocation) -------------------
__device__ float g_gi0[(size_t)TT * BB * GG];   // raw gi (NO b_ih; rec adds it)
__device__ float g_gi1[(size_t)TT * BB * GG];
__device__ float g_h0 [(size_t)TT * BB * HH];
__device__ float g_hst1[BB * HH];
// bf16 hi/lo W images, row-major [384][128] per layer
__device__ __nv_bfloat16 g_wh[2][384 * 128];
__device__ __nv_bfloat16 g_wl[2][384 * 128];

// ---------------- helpers ---------------------------------------------------
__device__ __forceinline__ u64 fma2p(u64 d, u64 a, u64 b) {
    asm("fma.rn.f32x2 %0, %1, %2, %0;" : "+l"(d) : "l"(a), "l"(b)); return d;
}
__device__ __forceinline__ float tanh_t(float x) {
    float y; asm("tanh.approx.f32 %0, %1;" : "=f"(y) : "f"(x)); return y;
}
__device__ __forceinline__ float sig_t(float x) {
    return fmaf(0.5f, tanh_t(0.5f * x), 0.5f);
}
__device__ __forceinline__ void split_pack(float x0, float x1, u32& hi, u32& lo) {
    __nv_bfloat16 h0 = __float2bfloat16(x0);
    __nv_bfloat16 h1 = __float2bfloat16(x1);
    __nv_bfloat16 l0 = __float2bfloat16(x0 - __bfloat162float(h0));
    __nv_bfloat16 l1 = __float2bfloat16(x1 - __bfloat162float(h1));
    hi = (u32)__bfloat16_as_ushort(h0) | ((u32)__bfloat16_as_ushort(h1) << 16);
    lo = (u32)__bfloat16_as_ushort(l0) | ((u32)__bfloat16_as_ushort(l1) << 16);
}

// ---------------- conversion: W -> bf16 hi/lo images ------------------------
__global__ void conv_w(const float* __restrict__ W0, const float* __restrict__ W1) {
    int i = blockIdx.x * blockDim.x + threadIdx.x;
    if (i >= 2 * 384 * 64) return;
    const int L = i / (384 * 64);
    const int rem = i % (384 * 64);
    const int j = rem >> 6;
    const int p = rem & 63;
    const float* W = L ? W1 : W0;
    u32 hi, lo;
    split_pack(W[(size_t)j * 128 + 2 * p], W[(size_t)j * 128 + 2 * p + 1], hi, lo);
    *(u32*)&g_wh[L][j * 128 + 2 * p] = hi;
    *(u32*)&g_wl[L][j * 128 + 2 * p] = lo;
}

// ---------------- WMMA GEMM (R12 winner, unchanged) --------------------------
__global__ void __launch_bounds__(256, 1) gemm_wmma(
    const float* __restrict__ act,
    int actMode,                     // 0: x layout [b][TT][128]; 1: h0 layout [t][b][128]
    const __nv_bfloat16* __restrict__ wh, const __nv_bfloat16* __restrict__ wl,
    float* __restrict__ dst, int t0, int t1, int nstripes)
{
    __shared__ __align__(16) __nv_bfloat16 s_ah[64 * APAD];
    __shared__ __align__(16) __nv_bfloat16 s_al[64 * APAD];
    const int tid = threadIdx.x;
    const int warp = tid >> 5;
    const int mtile = blockIdx.x / nstripes;
    const int stripe = blockIdx.x % nstripes;
    const int j0 = mtile * 128 + warp * 16;

    wmma::fragment<wmma::matrix_a, 16, 16, 16, __nv_bfloat16, wmma::row_major> wf_h[8], wf_l[8];
    #pragma unroll
    for (int k = 0; k < 8; k++) {
        wmma::load_matrix_sync(wf_h[k], wh + (size_t)j0 * 128 + k * 16, 128);
        wmma::load_matrix_sync(wf_l[k], wl + (size_t)j0 * 128 + k * 16, 128);
    }

    for (int t = t0 + stripe; t < t1; t += nstripes) {
        for (int i = tid; i < 64 * 32; i += 256) {       // units of 4 floats
            const int b = i >> 5;
            const int kq = (i & 31) * 4;
            const float* src = (actMode == 0)
                ? act + ((size_t)b * TT + t) * DD + kq
                : act + ((size_t)t * BB + b) * HH + kq;
            float4 v = *(const float4*)src;
            u32 h0, l0, h1, l1;
            split_pack(v.x, v.y, h0, l0);
            split_pack(v.z, v.w, h1, l1);
            *(u32*)&s_ah[b * APAD + kq]     = h0;
            *(u32*)&s_ah[b * APAD + kq + 2] = h1;
            *(u32*)&s_al[b * APAD + kq]     = l0;
            *(u32*)&s_al[b * APAD + kq + 2] = l1;
        }
        __syncthreads();

        wmma::fragment<wmma::accumulator, 16, 16, 16, float> acc[4];
        #pragma unroll
        for (int n = 0; n < 4; n++) wmma::fill_fragment(acc[n], 0.0f);

        #pragma unroll
        for (int k = 0; k < 8; k++) {
            #pragma unroll
            for (int n = 0; n < 4; n++) {
                wmma::fragment<wmma::matrix_b, 16, 16, 16, __nv_bfloat16, wmma::col_major> bh, bl;
                wmma::load_matrix_sync(bh, s_ah + n * 16 * APAD + k * 16, APAD);
                wmma::load_matrix_sync(bl, s_al + n * 16 * APAD + k * 16, APAD);
                wmma::mma_sync(acc[n], wf_h[k], bh, acc[n]);   // xh*wh
                wmma::mma_sync(acc[n], wf_h[k], bl, acc[n]);   // xl*wh
                wmma::mma_sync(acc[n], wf_l[k], bh, acc[n]);   // xh*wl
            }
        }

        float* dp = dst + (size_t)t * BB * GG + j0;
        #pragma unroll
        for (int n = 0; n < 4; n++)
            wmma::store_matrix_sync(dp + (size_t)(n * 16) * GG, acc[n],
                                    GG, wmma::mem_col_major);
        __syncthreads();
    }
}

// ---------------- rec chunk — compressed gate chain --------------------------
// Roles: j<128 r-rows (r kept in register by owner), 128-255 z-rows
// (z pre-sigmoided), 256-383 n-rows (raw gh_n). Branch-free select: all
// threads compute sig via MUFU.TANH; rows<256 store it, n-rows store raw acc.
// Post-barrier chain: LDS z/ghn + FMA + MUFU.TANH + blend + STS.
__global__ __launch_bounds__(384, 1) void rec_chunk(
    const float* __restrict__ Whh,
    const float* __restrict__ bhh,
    const float* __restrict__ bih,
    int layer, int c,
    float* __restrict__ hout)
{
    const int j = threadIdx.x;
    const int e = j & 127;
    const bool isGate = (j < 128);
    const int b = blockIdx.x;

    u64 w[64];
    {
        const ulonglong2* wr = (const ulonglong2*)(Whh + (size_t)j * 128);
        #pragma unroll
        for (int k = 0; k < 32; k++) { ulonglong2 v = wr[k]; w[2*k] = v.x; w[2*k+1] = v.y; }
    }
    const float bj = bhh[j];
    const float biOwn = bih[j];
    const float biN   = isGate ? bih[256 + e] : 0.0f;

    const float* gi = layer ? g_gi1 : g_gi0;
    const size_t S = (size_t)BB * GG;
    const float* pOwn = gi + (size_t)b * GG + j;
    const float* pN   = gi + (size_t)b * GG + 256 + e;   // gate threads only

    __shared__ __align__(16) float s_h[128];
    __shared__ float s_gh[384];

    const int t0 = c * CC, t1 = t0 + CC;

    float hreg = 0.0f;
    if (isGate) {
        if (c == 0) hreg = 0.0f;
        else if (layer == 0) hreg = g_h0[((size_t)(t0 - 1) * BB + b) * HH + e];
        else hreg = g_hst1[b * HH + e];
        s_h[e] = hreg;
    }
    __syncthreads();

    float gval = pOwn[(size_t)t0 * S];                    // bare load
    float gN   = isGate ? pN[(size_t)t0 * S] : 0.0f;      // bare load
    float* h0p = g_h0 + (size_t)b * HH + e;
    const ulonglong2* h16 = (const ulonglong2*)s_h;

    for (int t = t0; t < t1; t++) {
        // dot: gh row j = b_hh[j] + h . W_hh[j]   (2 fma2 chains)
        u64 a0, a1 = 0;
        asm("mov.b64 %0, {%1,%2};" : "=l"(a0) : "f"(bj), "f"(0.0f));
        #pragma unroll
        for (int k = 0; k < 32; k++) {
            ulonglong2 v = h16[k];
            a0 = fma2p(a0, v.x, w[2*k]);
            a1 = fma2p(a1, v.y, w[2*k+1]);
        }
        float acc;
        {
            float xl, xh, yl, yh;
            asm("mov.b64 {%0,%1}, %2;" : "=f"(xl), "=f"(xh) : "l"(a0));
            asm("mov.b64 {%0,%1}, %2;" : "=f"(yl), "=f"(yh) : "l"(a1));
            acc = (xl + xh) + (yl + yh);
        }

        // branch-free pre-barrier sigmoid (r & z rows); n rows store raw acc
        const float sv = sig_t(acc + gval + biOwn);       // MUFU.TANH-based
        s_gh[j] = (j < 256) ? sv : acc;
        const float r = sv;                               // valid for j<128 (r-row owner)
        __syncthreads();                                  // (A)

        if (isGate) {
            const float z   = s_gh[e + 128];              // pre-sigmoided
            const float ghn = s_gh[e + 256];              // raw (includes b_hh n)
            const float n = tanh_t(gN + biN + r * ghn);
            hreg = n + z * (hreg - n);
            s_h[e] = hreg;
            if (layer == 0) h0p[(size_t)t * BB * HH] = hreg;
        }
        __syncthreads();                                  // (B)

        if (t + 1 < t1) {
            const size_t off = (size_t)(t + 1) * S;
            gval = pOwn[off];                             // bare loads
            if (isGate) gN = pN[off];
        }
    }

    if (isGate) {
        if (layer == 1) g_hst1[b * HH + e] = hreg;
        if (c == NC - 1) hout[(size_t)b * HH + e] = hreg;
    }
}

// ---------------- launch (R12/R14 topology, unchanged) -----------------------
extern "C" void kernel_launch(void* const* d_in, const int* in_sizes, int n_in,
                              void* d_out, int out_size)
{
    const float* x     = (const float*)d_in[0];
    const float* W_ih0 = (const float*)d_in[1];
    const float* W_hh0 = (const float*)d_in[2];
    const float* b_ih0 = (const float*)d_in[3];
    const float* b_hh0 = (const float*)d_in[4];
    const float* W_ih1 = (const float*)d_in[5];
    const float* W_hh1 = (const float*)d_in[6];
    const float* b_ih1 = (const float*)d_in[7];
    const float* b_hh1 = (const float*)d_in[8];
    float* out = (float*)d_out;   // [L=2, B, H]

    static bool inited = false;
    static cudaStream_t sB, sC;
    static cudaEvent_t evFork, evG0, evR0[NC], evG1[NC];
    static __nv_bfloat16 *p_wh0, *p_wl0, *p_wh1, *p_wl1;
    static float *p_gi0, *p_gi1, *p_h0;
    if (!inited) {
        cudaStreamCreateWithFlags(&sB, cudaStreamNonBlocking);
        cudaStreamCreateWithFlags(&sC, cudaStreamNonBlocking);
        cudaEventCreateWithFlags(&evFork, cudaEventDisableTiming);
        cudaEventCreateWithFlags(&evG0, cudaEventDisableTiming);
        for (int i = 0; i < NC; i++) {
            cudaEventCreateWithFlags(&evR0[i], cudaEventDisableTiming);
            cudaEventCreateWithFlags(&evG1[i], cudaEventDisableTiming);
        }
        void* p;
        cudaGetSymbolAddress(&p, g_wh);  p_wh0 = (__nv_bfloat16*)p; p_wh1 = p_wh0 + 384 * 128;
        cudaGetSymbolAddress(&p, g_wl);  p_wl0 = (__nv_bfloat16*)p; p_wl1 = p_wl0 + 384 * 128;
        cudaGetSymbolAddress(&p, g_gi0); p_gi0 = (float*)p;
        cudaGetSymbolAddress(&p, g_gi1); p_gi1 = (float*)p;
        cudaGetSymbolAddress(&p, g_h0);  p_h0  = (float*)p;
        inited = true;
    }

    cudaEventRecord(evFork, 0);
    cudaStreamWaitEvent(sB, evFork, 0);
    cudaStreamWaitEvent(sC, evFork, 0);

    // Up-front: W conversion + ALL of gi0 (144 CTAs, then gone).
    conv_w<<<(2 * 384 * 64 + 255) / 256, 256, 0, sB>>>(W_ih0, W_ih1);
    gemm_wmma<<<3 * 48, 256, 0, sB>>>(x, /*actMode=*/0, p_wh0, p_wl0,
                                      p_gi0, 0, TT, 48);
    cudaEventRecord(evG0, sB);
    cudaStreamWaitEvent(sC, evG0, 0);

    for (int c = 0; c < NC; c++) {
        rec_chunk<<<64, 384, 0, sB>>>(W_hh0, b_hh0, b_ih0, /*layer=*/0, c, out);
        cudaEventRecord(evR0[c], sB);
    }
    for (int c = 0; c < NC; c++) {
        cudaStreamWaitEvent(sC, evR0[c], 0);
        gemm_wmma<<<3 * 4, 256, 0, sC>>>(p_h0, /*actMode=*/1, p_wh1, p_wl1,
                                         p_gi1, c * CC, (c + 1) * CC, 4);
        cudaEventRecord(evG1[c], sC);
    }
    for (int c = 0; c < NC; c++) {
        cudaStreamWaitEvent(0, evG1[c], 0);
        rec_chunk<<<64, 384, 0, 0>>>(W_hh1, b_hh1, b_ih1, /*layer=*/1, c, out + BB * HH);
    }
}